// round 13
// baseline (speedup 1.0000x reference)
#include <cuda_runtime.h>
#include <cuda_bf16.h>
#include <cstdint>

// Conv3x3(s1,p1) + PixelUnshuffle(2), warp-level mma.sync implicit GEMM, v3.
// x:(8,96,256,256)f32  W:(48,96,3,3)f32  out:(8,192,128,128)f32
// CTA: 32h x 32w tile = 4 subtiles of 8h x 32w (M=256), all 48 oc. 512 threads,
// 16 warps = 8 m-groups x 2 n-groups. K = 96 ic x 9 taps; fp32 = bf16_hi+bf16_lo,
// 3 passes (hh,hl,lh) ordered pass-major (no RAW chains), fp32 accum.
// Weights staged once per CTA (coalesced), A per 16-ic chunk with halo (10x34),
// next chunk's LDGs issued before this chunk's MMAs.

#define IC  96
#define HH  256
#define WW  256
#define OCN 48

#define A_CELLS 340            // 10 x 34
#define A_STR   24             // halfwords per cell (16 ic + 8 pad) = 48 B
#define A_HALF  16320          // 340*24*2 bytes (hi plane)
#define W_STR   104            // halfwords per oc row (96 ic + 8 pad) = 208 B
#define W_HALF  89856          // 9*48*104*2 bytes
#define OFF_W   (2 * A_HALF)   // 32640
#define SMEM_BYTES (OFF_W + 2 * W_HALF)   // 212352

#define NTHREADS 512
#define NSLOT 11               // ceil(340*16 / 512)

static __device__ __forceinline__ uint32_t smem_u32(const void* p) {
    uint32_t a;
    asm("{ .reg .u64 t; cvta.to.shared.u64 t, %1; cvt.u32.u64 %0, t; }" : "=r"(a) : "l"(p));
    return a;
}
static __device__ __forceinline__ void mma_bf16(float* d, const uint32_t* a, const uint32_t* b) {
    asm volatile(
        "mma.sync.aligned.m16n8k16.row.col.f32.bf16.bf16.f32 "
        "{%0,%1,%2,%3}, {%4,%5,%6,%7}, {%8,%9}, {%0,%1,%2,%3};"
        : "+f"(d[0]), "+f"(d[1]), "+f"(d[2]), "+f"(d[3])
        : "r"(a[0]), "r"(a[1]), "r"(a[2]), "r"(a[3]), "r"(b[0]), "r"(b[1]));
}
static __device__ __forceinline__ void ldsm_x4(uint32_t* r, uint32_t addr) {
    asm volatile("ldmatrix.sync.aligned.m8n8.x4.shared.b16 {%0,%1,%2,%3}, [%4];"
                 : "=r"(r[0]), "=r"(r[1]), "=r"(r[2]), "=r"(r[3]) : "r"(addr));
}
static __device__ __forceinline__ void ldsm_x2(uint32_t* r, uint32_t addr) {
    asm volatile("ldmatrix.sync.aligned.m8n8.x2.shared.b16 {%0,%1}, [%2];"
                 : "=r"(r[0]), "=r"(r[1]) : "r"(addr));
}
static __device__ __forceinline__ void split_bf16(float v, unsigned short& h, unsigned short& l) {
    __nv_bfloat16 hb = __float2bfloat16(v);
    __nv_bfloat16 lb = __float2bfloat16(v - __bfloat162float(hb));
    h = __bfloat16_as_ushort(hb);
    l = __bfloat16_as_ushort(lb);
}

__global__ void __launch_bounds__(NTHREADS, 1)
conv_unshuffle_mma3(const float* __restrict__ x,
                    const float* __restrict__ Wg,
                    float* __restrict__ out)
{
    extern __shared__ __align__(128) char sm[];
    const uint32_t smb = smem_u32(sm);
    unsigned short* wHi = (unsigned short*)(sm + OFF_W);
    unsigned short* wLo = (unsigned short*)(sm + OFF_W + W_HALF);

    const int tid  = threadIdx.x;
    const int lane = tid & 31;
    const int wid  = tid >> 5;
    const int mbase = (wid & 7) * 32;       // 8 m-groups of 32 rows
    const int nbase = (wid >> 3) * 24;      // 2 n-groups of 24 oc

    const int w0  = blockIdx.x * 32;
    const int h0c = blockIdx.y * 32;
    const int b   = blockIdx.z;
    const long long x_b = (long long)b * IC * HH * WW;

    // ---- per-thread A-staging slot metadata (constant across chunks) ----
    int gOff[NSLOT];       // ic*65536 + hr*256 + win
    int pk[NSLOT];         // hr | (validW<<8) | (slotValid<<9)
    uint32_t sAddr[NSLOT]; // byte offset into A hi plane
#pragma unroll
    for (int j = 0; j < NSLOT; ++j) {
        const int idx = tid + j * NTHREADS;
        const int sv  = (idx < A_CELLS * 16) ? 1 : 0;
        const int id2 = sv ? idx : 0;
        const int ic  = id2 / A_CELLS;
        const int cel = id2 - ic * A_CELLS;
        const int hr  = cel / 34;
        const int wc  = cel - hr * 34;
        const int win = w0 + wc - 1;
        const int vw  = ((unsigned)win < WW) ? 1 : 0;
        gOff[j]  = ic * (HH * WW) + hr * WW + win;
        pk[j]    = hr | (vw << 8) | (sv << 9);
        sAddr[j] = (uint32_t)(cel * (A_STR * 2) + ic * 2);
    }

    // ---- per-lane ldmatrix bases ----
    const int lrow  = lane & 15;
    const int lkoff = (lane >> 4) * 16;
    uint32_t aB[2];
#pragma unroll
    for (int mt = 0; mt < 2; ++mt) {
        const int m  = mbase + mt * 16 + lrow;
        const int hl = m >> 5;
        const int wl = m & 31;
        aB[mt] = smb + (uint32_t)((hl * 34 + wl) * (A_STR * 2)) + lkoff;
    }
    const uint32_t bB  = smb + OFF_W + (uint32_t)((nbase + lrow) * (W_STR * 2)) + lkoff;
    const uint32_t bB2 = smb + OFF_W + (uint32_t)((nbase + 16 + (lane & 7)) * (W_STR * 2))
                       + ((lane >> 3) & 1) * 16;

    float v[NSLOT];
    auto LOADA = [&](int h0s, int ic0) {
        const long long base = x_b + (long long)ic0 * (HH * WW) + (long long)(h0s - 1) * WW;
#pragma unroll
        for (int j = 0; j < NSLOT; ++j) {
            const int hin = h0s - 1 + (pk[j] & 255);
            const bool ok = (pk[j] & 512) && (pk[j] & 256) && ((unsigned)hin < HH);
            v[j] = ok ? __ldg(&x[base + gOff[j]]) : 0.0f;
        }
    };

    // prefetch A(subtile 0, chunk 0); LDGs fly during weight staging
    LOADA(h0c, 0);

    // ---- stage ALL weights once, coalesced LDG, scatter STS ----
    for (int idx = tid; idx < OCN * IC * 9; idx += NTHREADS) {
        const int oc  = idx / (IC * 9);
        const int r   = idx - oc * (IC * 9);
        const int ic  = r / 9;
        const int tap = r - ic * 9;
        unsigned short hi, lo;
        split_bf16(Wg[idx], hi, lo);
        const int ha = (tap * OCN + oc) * W_STR + ic;
        wHi[ha] = hi;
        wLo[ha] = lo;
    }

    for (int st = 0; st < 4; ++st) {
        const int h0s = h0c + st * 8;
        float acc[2][3][4];
#pragma unroll
        for (int mt = 0; mt < 2; ++mt)
#pragma unroll
            for (int nt = 0; nt < 3; ++nt)
#pragma unroll
                for (int e = 0; e < 4; ++e) acc[mt][nt][e] = 0.0f;

#pragma unroll 1
        for (int ch = 0; ch < 6; ++ch) {
            __syncthreads();   // prior chunk's MMA reads done (or W staging done)
            // split + store this chunk's A values
#pragma unroll
            for (int j = 0; j < NSLOT; ++j) {
                if (pk[j] & 512) {
                    unsigned short hi, lo;
                    split_bf16(v[j], hi, lo);
                    *(unsigned short*)(sm + sAddr[j])          = hi;
                    *(unsigned short*)(sm + A_HALF + sAddr[j]) = lo;
                }
            }
            __syncthreads();   // staging visible to all warps

            // issue next chunk's LDGs (in flight during MMA below)
            if (!(st == 3 && ch == 5)) {
                const int nst = (ch < 5) ? st : st + 1;
                const int nch = (ch < 5) ? ch + 1 : 0;
                LOADA(h0c + nst * 8, nch * 16);
            }

            // ---- MMA over 9 taps, pass-major (no back-to-back acc reuse) ----
            const uint32_t icb = (uint32_t)(ch * 32);   // 16 ic * 2 B
#pragma unroll
            for (int tap = 0; tap < 9; ++tap) {
                const int dy = tap / 3;
                const int dx = tap - dy * 3;
                const uint32_t aoff = (uint32_t)((dy * 34 + dx) * (A_STR * 2));
                const uint32_t woff = (uint32_t)(tap * (OCN * W_STR * 2)) + icb;

                uint32_t ah[2][4], al[2][4];
#pragma unroll
                for (int mt = 0; mt < 2; ++mt) {
                    ldsm_x4(ah[mt], aB[mt] + aoff);
                    ldsm_x4(al[mt], aB[mt] + aoff + A_HALF);
                }
                uint32_t bh01[4], bh2[2], bl01[4], bl2[2];
                ldsm_x4(bh01, bB  + woff);
                ldsm_x2(bh2,  bB2 + woff);
                ldsm_x4(bl01, bB  + woff + W_HALF);
                ldsm_x2(bl2,  bB2 + woff + W_HALF);

                uint32_t bh[3][2] = { {bh01[0], bh01[2]}, {bh01[1], bh01[3]}, {bh2[0], bh2[1]} };
                uint32_t bl[3][2] = { {bl01[0], bl01[2]}, {bl01[1], bl01[3]}, {bl2[0], bl2[1]} };

                // pass 1: ah * bh
#pragma unroll
                for (int mt = 0; mt < 2; ++mt)
#pragma unroll
                    for (int nt = 0; nt < 3; ++nt)
                        mma_bf16(acc[mt][nt], ah[mt], bh[nt]);
                // pass 2: ah * bl
#pragma unroll
                for (int mt = 0; mt < 2; ++mt)
#pragma unroll
                    for (int nt = 0; nt < 3; ++nt)
                        mma_bf16(acc[mt][nt], ah[mt], bl[nt]);
                // pass 3: al * bh
#pragma unroll
                for (int mt = 0; mt < 2; ++mt)
#pragma unroll
                    for (int nt = 0; nt < 3; ++nt)
                        mma_bf16(acc[mt][nt], al[mt], bh[nt]);
            }
        }

        // ---- epilogue: fused PixelUnshuffle(2) scatter for this subtile ----
        const int r0 = lane >> 2;
        const int c0 = (lane & 3) * 2;
#pragma unroll
        for (int mt = 0; mt < 2; ++mt) {
#pragma unroll
            for (int pair = 0; pair < 2; ++pair) {
                const int m  = mbase + mt * 16 + r0 + pair * 8;
                const int hl = m >> 5;
                const int wl = m & 31;
                const int h  = h0s + hl;
                const int w  = w0 + wl;
                const int cb = (h & 1) * 2 + (w & 1);
                const long long pxbase =
                    (((long long)b * 192 + cb) * 128 + (h >> 1)) * 128 + (w >> 1);
#pragma unroll
                for (int nt = 0; nt < 3; ++nt) {
                    const int oc0 = nbase + nt * 8 + c0;
                    out[pxbase + (long long)(oc0    ) * 4 * 128 * 128] = acc[mt][nt][pair * 2 + 0];
                    out[pxbase + (long long)(oc0 + 1) * 4 * 128 * 128] = acc[mt][nt][pair * 2 + 1];
                }
            }
        }
    }
}

extern "C" void kernel_launch(void* const* d_in, const int* in_sizes, int n_in,
                              void* d_out, int out_size)
{
    const float* x  = (const float*)d_in[0];
    const float* Wg = (const float*)d_in[1];
    float* out = (float*)d_out;

    static int configured = 0;
    if (!configured) {
        cudaFuncSetAttribute(conv_unshuffle_mma3,
                             cudaFuncAttributeMaxDynamicSharedMemorySize, SMEM_BYTES);
        configured = 1;
    }

    dim3 grid(WW / 32, HH / 32, 8);   // (8, 8, 8) = 512 CTAs
    conv_unshuffle_mma3<<<grid, NTHREADS, SMEM_BYTES>>>(x, Wg, out);
}

// round 15
// speedup vs baseline: 2.0175x; 2.0175x over previous
#include <cuda_runtime.h>
#include <cuda_fp16.h>
#include <cstdint>

// Conv3x3(s1,p1) + PixelUnshuffle(2), warp-level mma.sync implicit GEMM, v4.
// x:(8,96,256,256)f32  W:(48,96,3,3)f32  out:(8,192,128,128)f32
// CTA: 32h x 32w tile = 4 subtiles of 8h x 32w (M=256), all 48 oc. 512 threads,
// 16 warps = 8 m-groups x 2 n-groups. K = 96 ic x 9 taps.
// SINGLE-PASS fp16 (11-bit mantissa): predicted output rel err ~4e-4 < 1e-3.
// Weights staged once per CTA (coalesced), A per 16-ic chunk with halo (10x34),
// next chunk's LDGs issued before this chunk's MMAs.

#define IC  96
#define HH  256
#define WW  256
#define OCN 48

#define A_CELLS 340            // 10 x 34
#define A_STR   24             // halfwords per cell (16 ic + 8 pad) = 48 B
#define A_BYTESZ 16320         // 340*24*2
#define W_STR   104            // halfwords per oc row (96 ic + 8 pad) = 208 B
#define W_BYTESZ 89856         // 9*48*104*2
#define OFF_W   A_BYTESZ
#define SMEM_BYTES (OFF_W + W_BYTESZ)   // 106176

#define NTHREADS 512
#define NSLOT 11               // ceil(340*16 / 512)

static __device__ __forceinline__ uint32_t smem_u32(const void* p) {
    uint32_t a;
    asm("{ .reg .u64 t; cvta.to.shared.u64 t, %1; cvt.u32.u64 %0, t; }" : "=r"(a) : "l"(p));
    return a;
}
static __device__ __forceinline__ void mma_f16(float* d, const uint32_t* a, const uint32_t* b) {
    asm volatile(
        "mma.sync.aligned.m16n8k16.row.col.f32.f16.f16.f32 "
        "{%0,%1,%2,%3}, {%4,%5,%6,%7}, {%8,%9}, {%0,%1,%2,%3};"
        : "+f"(d[0]), "+f"(d[1]), "+f"(d[2]), "+f"(d[3])
        : "r"(a[0]), "r"(a[1]), "r"(a[2]), "r"(a[3]), "r"(b[0]), "r"(b[1]));
}
static __device__ __forceinline__ void ldsm_x4(uint32_t* r, uint32_t addr) {
    asm volatile("ldmatrix.sync.aligned.m8n8.x4.shared.b16 {%0,%1,%2,%3}, [%4];"
                 : "=r"(r[0]), "=r"(r[1]), "=r"(r[2]), "=r"(r[3]) : "r"(addr));
}
static __device__ __forceinline__ void ldsm_x2(uint32_t* r, uint32_t addr) {
    asm volatile("ldmatrix.sync.aligned.m8n8.x2.shared.b16 {%0,%1}, [%2];"
                 : "=r"(r[0]), "=r"(r[1]) : "r"(addr));
}
static __device__ __forceinline__ unsigned short to_h(float v) {
    return __half_as_ushort(__float2half_rn(v));
}

__global__ void __launch_bounds__(NTHREADS, 1)
conv_unshuffle_mma4(const float* __restrict__ x,
                    const float* __restrict__ Wg,
                    float* __restrict__ out)
{
    extern __shared__ __align__(128) char sm[];
    const uint32_t smb = smem_u32(sm);
    unsigned short* wH = (unsigned short*)(sm + OFF_W);

    const int tid  = threadIdx.x;
    const int lane = tid & 31;
    const int wid  = tid >> 5;
    const int mbase = (wid & 7) * 32;       // 8 m-groups of 32 rows
    const int nbase = (wid >> 3) * 24;      // 2 n-groups of 24 oc

    const int w0  = blockIdx.x * 32;
    const int h0c = blockIdx.y * 32;
    const int b   = blockIdx.z;
    const long long x_b = (long long)b * IC * HH * WW;

    // ---- per-thread A-staging slot metadata (constant across chunks) ----
    int gOff[NSLOT];       // ic*65536 + hr*256 + win
    int pk[NSLOT];         // hr | (validW<<8) | (slotValid<<9)
    uint32_t sAddr[NSLOT]; // byte offset into A plane
#pragma unroll
    for (int j = 0; j < NSLOT; ++j) {
        const int idx = tid + j * NTHREADS;
        const int sv  = (idx < A_CELLS * 16) ? 1 : 0;
        const int id2 = sv ? idx : 0;
        const int ic  = id2 / A_CELLS;
        const int cel = id2 - ic * A_CELLS;
        const int hr  = cel / 34;
        const int wc  = cel - hr * 34;
        const int win = w0 + wc - 1;
        const int vw  = ((unsigned)win < WW) ? 1 : 0;
        gOff[j]  = ic * (HH * WW) + hr * WW + win;
        pk[j]    = hr | (vw << 8) | (sv << 9);
        sAddr[j] = (uint32_t)(cel * (A_STR * 2) + ic * 2);
    }

    // ---- per-lane ldmatrix bases ----
    const int lrow  = lane & 15;
    const int lkoff = (lane >> 4) * 16;
    uint32_t aB[2];
#pragma unroll
    for (int mt = 0; mt < 2; ++mt) {
        const int m  = mbase + mt * 16 + lrow;
        const int hl = m >> 5;
        const int wl = m & 31;
        aB[mt] = smb + (uint32_t)((hl * 34 + wl) * (A_STR * 2)) + lkoff;
    }
    const uint32_t bB  = smb + OFF_W + (uint32_t)((nbase + lrow) * (W_STR * 2)) + lkoff;
    const uint32_t bB2 = smb + OFF_W + (uint32_t)((nbase + 16 + (lane & 7)) * (W_STR * 2))
                       + ((lane >> 3) & 1) * 16;

    float v[NSLOT];
    auto LOADA = [&](int h0s, int ic0) {
        const long long base = x_b + (long long)ic0 * (HH * WW) + (long long)(h0s - 1) * WW;
#pragma unroll
        for (int j = 0; j < NSLOT; ++j) {
            const int hin = h0s - 1 + (pk[j] & 255);
            const bool ok = (pk[j] & 512) && (pk[j] & 256) && ((unsigned)hin < HH);
            v[j] = ok ? __ldg(&x[base + gOff[j]]) : 0.0f;
        }
    };

    // prefetch A(subtile 0, chunk 0); LDGs fly during weight staging
    LOADA(h0c, 0);

    // ---- stage ALL weights once, coalesced LDG, scatter STS ----
    for (int idx = tid; idx < OCN * IC * 9; idx += NTHREADS) {
        const int oc  = idx / (IC * 9);
        const int r   = idx - oc * (IC * 9);
        const int ic  = r / 9;
        const int tap = r - ic * 9;
        wH[(tap * OCN + oc) * W_STR + ic] = to_h(Wg[idx]);
    }

    for (int st = 0; st < 4; ++st) {
        const int h0s = h0c + st * 8;
        float acc[2][3][4];
#pragma unroll
        for (int mt = 0; mt < 2; ++mt)
#pragma unroll
            for (int nt = 0; nt < 3; ++nt)
#pragma unroll
                for (int e = 0; e < 4; ++e) acc[mt][nt][e] = 0.0f;

#pragma unroll 1
        for (int ch = 0; ch < 6; ++ch) {
            __syncthreads();   // prior chunk's MMA reads done (or W staging done)
            // convert + store this chunk's A values
#pragma unroll
            for (int j = 0; j < NSLOT; ++j) {
                if (pk[j] & 512)
                    *(unsigned short*)(sm + sAddr[j]) = to_h(v[j]);
            }
            __syncthreads();   // staging visible to all warps

            // issue next chunk's LDGs (in flight during MMA below)
            if (!(st == 3 && ch == 5)) {
                const int nst = (ch < 5) ? st : st + 1;
                const int nch = (ch < 5) ? ch + 1 : 0;
                LOADA(h0c + nst * 8, nch * 16);
            }

            // ---- MMA over 9 taps, single fp16 pass ----
            const uint32_t icb = (uint32_t)(ch * 32);   // 16 ic * 2 B
#pragma unroll
            for (int tap = 0; tap < 9; ++tap) {
                const int dy = tap / 3;
                const int dx = tap - dy * 3;
                const uint32_t aoff = (uint32_t)((dy * 34 + dx) * (A_STR * 2));
                const uint32_t woff = (uint32_t)(tap * (OCN * W_STR * 2)) + icb;

                uint32_t ah[2][4];
                ldsm_x4(ah[0], aB[0] + aoff);
                ldsm_x4(ah[1], aB[1] + aoff);
                uint32_t b01[4], b2[2];
                ldsm_x4(b01, bB  + woff);
                ldsm_x2(b2,  bB2 + woff);

                uint32_t bf[3][2] = { {b01[0], b01[2]}, {b01[1], b01[3]}, {b2[0], b2[1]} };

#pragma unroll
                for (int mt = 0; mt < 2; ++mt)
#pragma unroll
                    for (int nt = 0; nt < 3; ++nt)
                        mma_f16(acc[mt][nt], ah[mt], bf[nt]);
            }
        }

        // ---- epilogue: fused PixelUnshuffle(2) scatter for this subtile ----
        const int r0 = lane >> 2;
        const int c0 = (lane & 3) * 2;
#pragma unroll
        for (int mt = 0; mt < 2; ++mt) {
#pragma unroll
            for (int pair = 0; pair < 2; ++pair) {
                const int m  = mbase + mt * 16 + r0 + pair * 8;
                const int hl = m >> 5;
                const int wl = m & 31;
                const int h  = h0s + hl;
                const int w  = w0 + wl;
                const int cb = (h & 1) * 2 + (w & 1);
                const long long pxbase =
                    (((long long)b * 192 + cb) * 128 + (h >> 1)) * 128 + (w >> 1);
#pragma unroll
                for (int nt = 0; nt < 3; ++nt) {
                    const int oc0 = nbase + nt * 8 + c0;
                    out[pxbase + (long long)(oc0    ) * 4 * 128 * 128] = acc[mt][nt][pair * 2 + 0];
                    out[pxbase + (long long)(oc0 + 1) * 4 * 128 * 128] = acc[mt][nt][pair * 2 + 1];
                }
            }
        }
    }
}

extern "C" void kernel_launch(void* const* d_in, const int* in_sizes, int n_in,
                              void* d_out, int out_size)
{
    const float* x  = (const float*)d_in[0];
    const float* Wg = (const float*)d_in[1];
    float* out = (float*)d_out;

    static int configured = 0;
    if (!configured) {
        cudaFuncSetAttribute(conv_unshuffle_mma4,
                             cudaFuncAttributeMaxDynamicSharedMemorySize, SMEM_BYTES);
        configured = 1;
    }

    dim3 grid(WW / 32, HH / 32, 8);   // (8, 8, 8) = 512 CTAs
    conv_unshuffle_mma4<<<grid, NTHREADS, SMEM_BYTES>>>(x, Wg, out);
}

// round 16
// speedup vs baseline: 2.4261x; 1.2025x over previous
#include <cuda_runtime.h>
#include <cuda_fp16.h>
#include <cstdint>

// Conv3x3(s1,p1) + PixelUnshuffle(2), warp-level mma.sync implicit GEMM, v5.
// x:(8,96,256,256)f32  W:(48,96,3,3)f32  out:(8,192,128,128)f32
// CTA: 32h x 32w tile = 4 subtiles of 8h x 32w (M=256), all 48 oc. 512 threads,
// 16 warps = 8 m-groups x 2 n-groups. K = 96 ic x 9 taps, single-pass fp16.
// v5: double-buffered A smem (1 syncthreads per chunk), vectorized conflict-free
// staging (8-ic blocks, STS.128), stage overlaps other warps' MMAs.

#define IC  96
#define HH  256
#define WW  256
#define OCN 48

#define A_CELLS 340            // 10 x 34
#define A_STR   24             // halfwords per cell (16 ic + 8 pad) = 48 B
#define A_BYTESZ 16320         // 340*24*2 per buffer
#define W_STR   104            // halfwords per oc row (96 ic + 8 pad) = 208 B
#define W_BYTESZ 89856         // 9*48*104*2
#define OFF_W   (2 * A_BYTESZ) // two A buffers
#define SMEM_BYTES (OFF_W + W_BYTESZ)   // 122496

#define NTHREADS 512
#define NUNIT 680              // 340 cells x 2 ic-blocks

static __device__ __forceinline__ uint32_t smem_u32(const void* p) {
    uint32_t a;
    asm("{ .reg .u64 t; cvta.to.shared.u64 t, %1; cvt.u32.u64 %0, t; }" : "=r"(a) : "l"(p));
    return a;
}
static __device__ __forceinline__ void mma_f16(float* d, const uint32_t* a, const uint32_t* b) {
    asm volatile(
        "mma.sync.aligned.m16n8k16.row.col.f32.f16.f16.f32 "
        "{%0,%1,%2,%3}, {%4,%5,%6,%7}, {%8,%9}, {%0,%1,%2,%3};"
        : "+f"(d[0]), "+f"(d[1]), "+f"(d[2]), "+f"(d[3])
        : "r"(a[0]), "r"(a[1]), "r"(a[2]), "r"(a[3]), "r"(b[0]), "r"(b[1]));
}
static __device__ __forceinline__ void ldsm_x4(uint32_t* r, uint32_t addr) {
    asm volatile("ldmatrix.sync.aligned.m8n8.x4.shared.b16 {%0,%1,%2,%3}, [%4];"
                 : "=r"(r[0]), "=r"(r[1]), "=r"(r[2]), "=r"(r[3]) : "r"(addr));
}
static __device__ __forceinline__ void ldsm_x2(uint32_t* r, uint32_t addr) {
    asm volatile("ldmatrix.sync.aligned.m8n8.x2.shared.b16 {%0,%1}, [%2];"
                 : "=r"(r[0]), "=r"(r[1]) : "r"(addr));
}
static __device__ __forceinline__ unsigned short to_h(float v) {
    return __half_as_ushort(__float2half_rn(v));
}

__global__ void __launch_bounds__(NTHREADS, 1)
conv_unshuffle_mma5(const float* __restrict__ x,
                    const float* __restrict__ Wg,
                    float* __restrict__ out)
{
    extern __shared__ __align__(128) char sm[];
    const uint32_t smb = smem_u32(sm);
    unsigned short* wH = (unsigned short*)(sm + OFF_W);

    const int tid  = threadIdx.x;
    const int lane = tid & 31;
    const int wid  = tid >> 5;
    const int mbase = (wid & 7) * 32;       // 8 m-groups of 32 rows
    const int nbase = (wid >> 3) * 24;      // 2 n-groups of 24 oc

    const int w0  = blockIdx.x * 32;
    const int h0c = blockIdx.y * 32;
    const int b   = blockIdx.z;
    const long long x_b = (long long)b * IC * HH * WW;

    // ---- per-thread staging unit metadata: unit = (8-ic block, cell) ----
    // u = tid + j*512; cel = u % 340 (consecutive tid -> consecutive cell -> coalesced)
    int gOffU[2];          // icb*8*HW + hr*WW + win
    int pkU[2];            // hr | (validW<<8) | (unitValid<<9)
    uint32_t sAddrU[2];    // byte offset into A buffer
#pragma unroll
    for (int j = 0; j < 2; ++j) {
        const int u  = tid + j * NTHREADS;
        const int uv = (u < NUNIT) ? 1 : 0;
        const int u2 = uv ? u : 0;
        const int icb = u2 / A_CELLS;
        const int cel = u2 - icb * A_CELLS;
        const int hr  = cel / 34;
        const int wc  = cel - hr * 34;
        const int win = w0 + wc - 1;
        const int vw  = ((unsigned)win < WW) ? 1 : 0;
        gOffU[j]  = icb * 8 * (HH * WW) + hr * WW + win;
        pkU[j]    = hr | (vw << 8) | (uv << 9);
        sAddrU[j] = (uint32_t)(cel * (A_STR * 2) + icb * 16);
    }

    // ---- per-lane ldmatrix bases (buffer 0) ----
    const int lrow  = lane & 15;
    const int lkoff = (lane >> 4) * 16;
    uint32_t aB[2];
#pragma unroll
    for (int mt = 0; mt < 2; ++mt) {
        const int m  = mbase + mt * 16 + lrow;
        const int hl = m >> 5;
        const int wl = m & 31;
        aB[mt] = smb + (uint32_t)((hl * 34 + wl) * (A_STR * 2)) + lkoff;
    }
    const uint32_t bB  = smb + OFF_W + (uint32_t)((nbase + lrow) * (W_STR * 2)) + lkoff;
    const uint32_t bB2 = smb + OFF_W + (uint32_t)((nbase + 16 + (lane & 7)) * (W_STR * 2))
                       + ((lane >> 3) & 1) * 16;

    float v[2][8];
    auto LOADA = [&](int h0s, int ic0) {
        const long long base = x_b + (long long)ic0 * (HH * WW) + (long long)(h0s - 1) * WW;
#pragma unroll
        for (int j = 0; j < 2; ++j) {
            const int hin = h0s - 1 + (pkU[j] & 255);
            const bool ok = (pkU[j] & 512) && (pkU[j] & 256) && ((unsigned)hin < HH);
#pragma unroll
            for (int e = 0; e < 8; ++e)
                v[j][e] = ok ? __ldg(&x[base + gOffU[j] + (long long)e * (HH * WW)]) : 0.0f;
        }
    };

    // prefetch A(subtile 0, chunk 0); LDGs fly during weight staging
    LOADA(h0c, 0);

    // ---- stage ALL weights once, coalesced LDG, scatter STS ----
    for (int idx = tid; idx < OCN * IC * 9; idx += NTHREADS) {
        const int oc  = idx / (IC * 9);
        const int r   = idx - oc * (IC * 9);
        const int ic  = r / 9;
        const int tap = r - ic * 9;
        wH[(tap * OCN + oc) * W_STR + ic] = to_h(Wg[idx]);
    }

    for (int st = 0; st < 4; ++st) {
        float acc[2][3][4];
#pragma unroll
        for (int mt = 0; mt < 2; ++mt)
#pragma unroll
            for (int nt = 0; nt < 3; ++nt)
#pragma unroll
                for (int e = 0; e < 4; ++e) acc[mt][nt][e] = 0.0f;

#pragma unroll 1
        for (int ch = 0; ch < 6; ++ch) {
            const int it = st * 6 + ch;
            const uint32_t bufoff = (uint32_t)((it & 1) * A_BYTESZ);

            // ---- stage this chunk (v -> smem buffer), STS.128 conflict-free ----
#pragma unroll
            for (int j = 0; j < 2; ++j) {
                if (pkU[j] & 512) {
                    __half2 h0 = __floats2half2_rn(v[j][0], v[j][1]);
                    __half2 h1 = __floats2half2_rn(v[j][2], v[j][3]);
                    __half2 h2 = __floats2half2_rn(v[j][4], v[j][5]);
                    __half2 h3 = __floats2half2_rn(v[j][6], v[j][7]);
                    uint4 q;
                    q.x = *(uint32_t*)&h0;  q.y = *(uint32_t*)&h1;
                    q.z = *(uint32_t*)&h2;  q.w = *(uint32_t*)&h3;
                    *(uint4*)(sm + bufoff + sAddrU[j]) = q;
                }
            }
            __syncthreads();   // single barrier: staging visible; prev-prev MMAs done

            // issue next chunk's LDGs (in flight during MMA below)
            if (it < 23) {
                const int nst = (ch < 5) ? st : st + 1;
                const int nch = (ch < 5) ? ch + 1 : 0;
                LOADA(h0c + nst * 8, nch * 16);
            }

            // ---- MMA over 9 taps, single fp16 pass ----
            const uint32_t icb = (uint32_t)(ch * 32);   // 16 ic * 2 B
#pragma unroll
            for (int tap = 0; tap < 9; ++tap) {
                const int dy = tap / 3;
                const int dx = tap - dy * 3;
                const uint32_t aoff = bufoff + (uint32_t)((dy * 34 + dx) * (A_STR * 2));
                const uint32_t woff = (uint32_t)(tap * (OCN * W_STR * 2)) + icb;

                uint32_t ah[2][4];
                ldsm_x4(ah[0], aB[0] + aoff);
                ldsm_x4(ah[1], aB[1] + aoff);
                uint32_t b01[4], b2[2];
                ldsm_x4(b01, bB  + woff);
                ldsm_x2(b2,  bB2 + woff);

                uint32_t bf[3][2] = { {b01[0], b01[2]}, {b01[1], b01[3]}, {b2[0], b2[1]} };

#pragma unroll
                for (int mt = 0; mt < 2; ++mt)
#pragma unroll
                    for (int nt = 0; nt < 3; ++nt)
                        mma_f16(acc[mt][nt], ah[mt], bf[nt]);
            }
        }

        // ---- epilogue: fused PixelUnshuffle(2) scatter for this subtile ----
        const int h0s = h0c + st * 8;
        const int r0 = lane >> 2;
        const int c0 = (lane & 3) * 2;
#pragma unroll
        for (int mt = 0; mt < 2; ++mt) {
#pragma unroll
            for (int pair = 0; pair < 2; ++pair) {
                const int m  = mbase + mt * 16 + r0 + pair * 8;
                const int hl = m >> 5;
                const int wl = m & 31;
                const int h  = h0s + hl;
                const int w  = w0 + wl;
                const int cb = (h & 1) * 2 + (w & 1);
                const long long pxbase =
                    (((long long)b * 192 + cb) * 128 + (h >> 1)) * 128 + (w >> 1);
#pragma unroll
                for (int nt = 0; nt < 3; ++nt) {
                    const int oc0 = nbase + nt * 8 + c0;
                    out[pxbase + (long long)(oc0    ) * 4 * 128 * 128] = acc[mt][nt][pair * 2 + 0];
                    out[pxbase + (long long)(oc0 + 1) * 4 * 128 * 128] = acc[mt][nt][pair * 2 + 1];
                }
            }
        }
    }
}

extern "C" void kernel_launch(void* const* d_in, const int* in_sizes, int n_in,
                              void* d_out, int out_size)
{
    const float* x  = (const float*)d_in[0];
    const float* Wg = (const float*)d_in[1];
    float* out = (float*)d_out;

    static int configured = 0;
    if (!configured) {
        cudaFuncSetAttribute(conv_unshuffle_mma5,
                             cudaFuncAttributeMaxDynamicSharedMemorySize, SMEM_BYTES);
        configured = 1;
    }

    dim3 grid(WW / 32, HH / 32, 8);   // (8, 8, 8) = 512 CTAs
    conv_unshuffle_mma5<<<grid, NTHREADS, SMEM_BYTES>>>(x, Wg, out);
}